// round 9
// baseline (speedup 1.0000x reference)
#include <cuda_runtime.h>

// NeuralBPDecoder: sparse BP, 2 launches.
// k_build: stream H (537 MB, 8-deep uint4 batches) -> ELL adjacency (atomics).
//          Counters zero at entry (static init on call 1; bp_persist epilogue
//          re-zeroes them every call -> graph-replay deterministic).
// bp_persist (148 x 1024, co-resident, software grid barrier):
//   sort lists -> hoist per-node state into registers -> 15 x two phases ->
//   sigmoid output. Node layout: 16 lanes per node, lane owns a float2 batch
//   pair; block-strided node ownership balances all 148 SMs in both phases.

#define NC 8192
#define NV 16384
#define NB 32
#define RD 64
#define CD 48
#define ITERS 15
#define NBLK 148
#define NTHR 1024
#define WPB  (NTHR / 32)

#define B_BLOCKS 2048
#define B_THREADS 256
#define U 8
#define FULL 0xffffffffu

__device__ int   g_row_cnt[NC];
__device__ int   g_row_cols[NC * RD];
__device__ int   g_col_cnt[NV];
__device__ int   g_col_rows[NV * CD];
__device__ float g_vT[NV * NB];         // beliefs mailbox, (v, b) rows of 128B
__device__ float g_cT[NC * NB];         // check messages, (c, b)

__device__ unsigned g_bar_arrive;
__device__ unsigned g_bar_gen;

__device__ __forceinline__ void grid_sync() {
    __syncthreads();
    if (threadIdx.x == 0) {
        __threadfence();
        volatile unsigned* genp = &g_bar_gen;
        unsigned gen = *genp;
        if (atomicAdd(&g_bar_arrive, 1) == NBLK - 1) {
            g_bar_arrive = 0;
            __threadfence();
            atomicAdd(&g_bar_gen, 1);
        } else {
            while (*genp == gen) { }
        }
        __threadfence();
    }
    __syncthreads();
}

__device__ __forceinline__ void emit_quad(long i, uint4 h) {
    long base = i * 4;
    unsigned vals[4] = {h.x, h.y, h.z, h.w};
    #pragma unroll
    for (int k = 0; k < 4; k++) {
        if (vals[k]) {
            long e = base + k;
            int c = (int)(e >> 14);
            int v = (int)(e & (NV - 1));
            int rs = atomicAdd(&g_row_cnt[c], 1);
            if (rs < RD) g_row_cols[c * RD + rs] = v;
            int cs = atomicAdd(&g_col_cnt[v], 1);
            if (cs < CD) g_col_rows[v * CD + cs] = c;
        }
    }
}

__global__ void __launch_bounds__(B_THREADS)
k_build(const uint4* __restrict__ H4) {
    const long n4 = (long)NC * NV / 4;
    const long stride = (long)B_BLOCKS * B_THREADS;
    long i = (long)blockIdx.x * B_THREADS + threadIdx.x;

    for (; i + (U - 1) * stride < n4; i += U * stride) {
        uint4 h[U];
        #pragma unroll
        for (int u = 0; u < U; u++)
            h[u] = __ldcs(&H4[i + u * stride]);
        #pragma unroll
        for (int u = 0; u < U; u++) {
            if (h[u].x | h[u].y | h[u].z | h[u].w)
                emit_quad(i + u * stride, h[u]);
        }
    }
    for (; i < n4; i += stride) {
        uint4 h = __ldcs(&H4[i]);
        if (h.x | h.y | h.z | h.w)
            emit_quad(i, h);
    }
}

__device__ __forceinline__ float2 f2add(float2 a, float2 b) {
    a.x += b.x; a.y += b.y; return a;
}

__global__ void __launch_bounds__(NTHR, 1)
bp_persist(const float* __restrict__ synd, const float* __restrict__ llr,
           const float* __restrict__ wvc_p, const float* __restrict__ wcv_p,
           const float* __restrict__ damp_p, float* __restrict__ out) {
    const int tid  = blockIdx.x * NTHR + threadIdx.x;
    const int gsz  = NBLK * NTHR;
    const int wib  = threadIdx.x >> 5;     // warp in block
    const int lane = threadIdx.x & 31;
    const int sub  = lane & 15;            // float2 slot (batch pair)
    const int grp  = lane >> 4;            // node within pair
    const int gb   = lane & 16;            // shfl base of this 16-lane group

    const float wvc  = __ldg(wvc_p);
    const float wcv  = __ldg(wcv_p);
    const float damp = __ldg(damp_p);
    const float omd  = 1.0f - damp;

    float2* __restrict__ vT2 = (float2*)g_vT;
    float2* __restrict__ cT2 = (float2*)g_cT;

    // ---- sort adjacency lists (local staging; deterministic order) ----
    {
        int tmp[RD];
        for (int i = tid; i < NV; i += gsz) {
            int n = min(g_col_cnt[i], CD);
            g_col_cnt[i] = n;
            int* a = &g_col_rows[i * CD];
            for (int j = 0; j < n; j++) tmp[j] = a[j];
            for (int j = 1; j < n; j++) {
                int key = tmp[j]; int k = j - 1;
                while (k >= 0 && tmp[k] > key) { tmp[k + 1] = tmp[k]; k--; }
                tmp[k + 1] = key;
            }
            for (int j = 0; j < n; j++) a[j] = tmp[j];
        }
        for (int i = tid; i < NC; i += gsz) {
            int n = min(g_row_cnt[i], RD);
            g_row_cnt[i] = n;
            int* a = &g_row_cols[i * RD];
            for (int j = 0; j < n; j++) tmp[j] = a[j];
            for (int j = 1; j < n; j++) {
                int key = tmp[j]; int k = j - 1;
                while (k >= 0 && tmp[k] > key) { tmp[k + 1] = tmp[k]; k--; }
                tmp[k + 1] = key;
            }
            for (int j = 0; j < n; j++) a[j] = tmp[j];
        }
    }
    grid_sync();

    // ---- block-strided ownership + register hoist ----
    // checks: pair cp = blockIdx + wib*148, cp < NC/2; c = cp*2 + grp
    const int cp   = blockIdx.x + wib * NBLK;
    const bool chas = (cp < NC / 2);
    int c = 0, cdeg = 0, cidx0 = 0, cidx1 = 0;
    float2 csgn = make_float2(0.f, 0.f);
    if (chas) {
        c     = cp * 2 + grp;
        cdeg  = g_row_cnt[c];
        cidx0 = g_row_cols[c * RD + sub];
        cidx1 = g_row_cols[c * RD + 16 + sub];
        csgn.x = 1.0f - 2.0f * synd[(2 * sub + 0) * NC + c];
        csgn.y = 1.0f - 2.0f * synd[(2 * sub + 1) * NC + c];
    }
    // vars: 2 rounds, pair vp = blockIdx + (wib + 32k)*148, vp < NV/2
    int    vv[2], vdeg[2], vidx[2];
    bool   vhas[2];
    float2 vch[2], vb[2];
    #pragma unroll
    for (int r = 0; r < 2; r++) {
        int vp  = blockIdx.x + (wib + r * WPB) * NBLK;
        vhas[r] = (vp < NV / 2);
        vv[r] = 0; vdeg[r] = 0; vidx[r] = 0;
        vch[r] = make_float2(0.f, 0.f); vb[r] = vch[r];
        if (vhas[r]) {
            int v   = vp * 2 + grp;
            vv[r]   = v;
            vdeg[r] = g_col_cnt[v];
            vidx[r] = g_col_rows[v * CD + sub];
            vch[r].x = llr[(2 * sub + 0) * NV + v];
            vch[r].y = llr[(2 * sub + 1) * NV + v];
            vb[r] = vch[r];
            vT2[(v << 4) + sub] = vb[r];       // publish initial beliefs
        }
    }
    grid_sync();

    // ---- BP iterations ----
    for (int it = 0; it < ITERS; it++) {
        // v -> c : lane sums its batch pair over the check's edges
        if (chas) {
            float2 a0 = make_float2(0.f, 0.f);
            float2 a1 = make_float2(0.f, 0.f);
            #pragma unroll
            for (int m = 0; m < 16; m += 2) {
                int i0 = __shfl_sync(FULL, cidx0, gb + m);
                int i1 = __shfl_sync(FULL, cidx0, gb + m + 1);
                if (m     < cdeg) a0 = f2add(a0, vT2[(i0 << 4) + sub]);
                if (m + 1 < cdeg) a1 = f2add(a1, vT2[(i1 << 4) + sub]);
            }
            if (__any_sync(FULL, cdeg > 16)) {
                #pragma unroll
                for (int m = 0; m < 16; m += 2) {
                    int i0 = __shfl_sync(FULL, cidx1, gb + m);
                    int i1 = __shfl_sync(FULL, cidx1, gb + m + 1);
                    if (16 + m     < cdeg) a0 = f2add(a0, vT2[(i0 << 4) + sub]);
                    if (16 + m + 1 < cdeg) a1 = f2add(a1, vT2[(i1 << 4) + sub]);
                }
            }
            for (int j = 32; j < cdeg; j++) {          // very rare tail
                int idx = g_row_cols[c * RD + j];
                a0 = f2add(a0, vT2[(idx << 4) + sub]);
            }
            float2 acc = f2add(a0, a1);
            float2 m2;
            m2.x = csgn.x * tanhf(0.5f * wvc * acc.x);
            m2.y = csgn.y * tanhf(0.5f * wvc * acc.y);
            cT2[(c << 4) + sub] = m2;
        }
        grid_sync();

        // c -> v + damped update
        #pragma unroll
        for (int r = 0; r < 2; r++) {
            if (vhas[r]) {
                int deg = vdeg[r];
                float2 a0 = make_float2(0.f, 0.f);
                float2 a1 = make_float2(0.f, 0.f);
                #pragma unroll
                for (int m = 0; m < 16; m += 2) {
                    int i0 = __shfl_sync(FULL, vidx[r], gb + m);
                    int i1 = __shfl_sync(FULL, vidx[r], gb + m + 1);
                    if (m     < deg) a0 = f2add(a0, cT2[(i0 << 4) + sub]);
                    if (m + 1 < deg) a1 = f2add(a1, cT2[(i1 << 4) + sub]);
                }
                for (int j = 16; j < deg; j++) {       // rare tail
                    int idx = g_col_rows[vv[r] * CD + j];
                    a0 = f2add(a0, cT2[(idx << 4) + sub]);
                }
                float2 acc = f2add(a0, a1);
                vb[r].x = damp * vb[r].x + omd * (vch[r].x + wcv * acc.x);
                vb[r].y = damp * vb[r].y + omd * (vch[r].y + wcv * acc.y);
                vT2[(vv[r] << 4) + sub] = vb[r];
            }
        }
        grid_sync();
    }

    // ---- output sigmoid(-v) from registers, (b, v) order ----
    #pragma unroll
    for (int r = 0; r < 2; r++) {
        if (vhas[r]) {
            int v = vv[r];
            out[(2 * sub + 0) * NV + v] = 1.0f / (1.0f + expf(vb[r].x));
            out[(2 * sub + 1) * NV + v] = 1.0f / (1.0f + expf(vb[r].y));
        }
    }

    // ---- re-zero degree counters for the next call's k_build ----
    for (int i = tid; i < NV; i += gsz) {
        g_col_cnt[i] = 0;
        if (i < NC) g_row_cnt[i] = 0;
    }
}

extern "C" void kernel_launch(void* const* d_in, const int* in_sizes, int n_in,
                              void* d_out, int out_size) {
    const float* synd = (const float*)d_in[0];
    const float* H    = (const float*)d_in[1];
    const float* llr  = (const float*)d_in[2];
    const float* wvc  = (const float*)d_in[3];
    const float* wcv  = (const float*)d_in[4];
    const float* damp = (const float*)d_in[5];
    float* out = (float*)d_out;

    k_build<<<B_BLOCKS, B_THREADS>>>((const uint4*)H);
    bp_persist<<<NBLK, NTHR>>>(synd, llr, wvc, wcv, damp, out);
}

// round 10
// speedup vs baseline: 1.2487x; 1.2487x over previous
#include <cuda_runtime.h>

// NeuralBPDecoder: sparse BP, 2 launches.
// k_build: stream H (537 MB, 8-deep uint4 batches) -> ELL adjacency (atomics).
//          Counters zero at entry (static init on call 1; bp_persist epilogue
//          re-zeroes them -> graph-replay deterministic).
// bp_persist (148 x 1024, co-resident, software grid barrier):
//   sort lists -> hoist per-node state into registers -> 15 x two phases ->
//   sigmoid output. Node layout: warp = 4 groups x 8 lanes; group owns one
//   node; lane owns a float4 batch-quad (max data per load instruction).
//   Block-strided node ownership balances all 148 SMs in both phases.

#define NC 8192
#define NV 16384
#define NB 32
#define RD 64
#define CD 48
#define ITERS 15
#define NBLK 148
#define NTHR 1024
#define WPB  (NTHR / 32)

#define B_BLOCKS 2048
#define B_THREADS 256
#define U 8
#define FULL 0xffffffffu

__device__ int   g_row_cnt[NC];
__device__ int   g_row_cols[NC * RD];
__device__ int   g_col_cnt[NV];
__device__ int   g_col_rows[NV * CD];
__device__ float g_vT[NV * NB];         // beliefs mailbox, (v, b) 128B rows
__device__ float g_cT[NC * NB];         // check messages, (c, b)

__device__ unsigned g_bar_arrive;
__device__ unsigned g_bar_gen;

__device__ __forceinline__ void grid_sync() {
    __syncthreads();
    if (threadIdx.x == 0) {
        __threadfence();
        volatile unsigned* genp = &g_bar_gen;
        unsigned gen = *genp;
        if (atomicAdd(&g_bar_arrive, 1) == NBLK - 1) {
            g_bar_arrive = 0;
            __threadfence();
            atomicAdd(&g_bar_gen, 1);
        } else {
            while (*genp == gen) { }
        }
        __threadfence();
    }
    __syncthreads();
}

__device__ __forceinline__ void emit_quad(long i, uint4 h) {
    long base = i * 4;
    unsigned vals[4] = {h.x, h.y, h.z, h.w};
    #pragma unroll
    for (int k = 0; k < 4; k++) {
        if (vals[k]) {
            long e = base + k;
            int c = (int)(e >> 14);
            int v = (int)(e & (NV - 1));
            int rs = atomicAdd(&g_row_cnt[c], 1);
            if (rs < RD) g_row_cols[c * RD + rs] = v;
            int cs = atomicAdd(&g_col_cnt[v], 1);
            if (cs < CD) g_col_rows[v * CD + cs] = c;
        }
    }
}

__global__ void __launch_bounds__(B_THREADS)
k_build(const uint4* __restrict__ H4) {
    const long n4 = (long)NC * NV / 4;
    const long stride = (long)B_BLOCKS * B_THREADS;
    long i = (long)blockIdx.x * B_THREADS + threadIdx.x;

    for (; i + (U - 1) * stride < n4; i += U * stride) {
        uint4 h[U];
        #pragma unroll
        for (int u = 0; u < U; u++)
            h[u] = __ldcs(&H4[i + u * stride]);
        #pragma unroll
        for (int u = 0; u < U; u++) {
            if (h[u].x | h[u].y | h[u].z | h[u].w)
                emit_quad(i + u * stride, h[u]);
        }
    }
    for (; i < n4; i += stride) {
        uint4 h = __ldcs(&H4[i]);
        if (h.x | h.y | h.z | h.w)
            emit_quad(i, h);
    }
}

// tanh(y) = 1 - 2/(exp(2y)+1); callers pass z = 2y. ~1e-6 accurate, ~4 ops.
__device__ __forceinline__ float tanh_of_half(float z) {
    return 1.0f - __fdividef(2.0f, __expf(z) + 1.0f);
}

__global__ void __launch_bounds__(NTHR, 1)
bp_persist(const float* __restrict__ synd, const float* __restrict__ llr,
           const float* __restrict__ wvc_p, const float* __restrict__ wcv_p,
           const float* __restrict__ damp_p, float* __restrict__ out) {
    const int tid   = blockIdx.x * NTHR + threadIdx.x;
    const int gsz   = NBLK * NTHR;
    const int wib   = threadIdx.x >> 5;   // warp in block
    const int lane  = threadIdx.x & 31;
    const int sub   = lane & 7;           // float4 slot (batch quad)
    const int grp   = lane >> 3;          // node within quad
    const int gbase = lane & 24;          // shfl base of this 8-lane group

    const float wvc  = __ldg(wvc_p);
    const float wcv  = __ldg(wcv_p);
    const float damp = __ldg(damp_p);
    const float omd  = 1.0f - damp;

    float4* __restrict__ vT4 = (float4*)g_vT;
    float4* __restrict__ cT4 = (float4*)g_cT;

    // ---- sort adjacency lists (local staging; deterministic order) ----
    {
        int tmp[RD];
        for (int i = tid; i < NV; i += gsz) {
            int n = min(g_col_cnt[i], CD);
            g_col_cnt[i] = n;
            int* a = &g_col_rows[i * CD];
            for (int j = 0; j < n; j++) tmp[j] = a[j];
            for (int j = 1; j < n; j++) {
                int key = tmp[j]; int k = j - 1;
                while (k >= 0 && tmp[k] > key) { tmp[k + 1] = tmp[k]; k--; }
                tmp[k + 1] = key;
            }
            for (int j = 0; j < n; j++) a[j] = tmp[j];
        }
        for (int i = tid; i < NC; i += gsz) {
            int n = min(g_row_cnt[i], RD);
            g_row_cnt[i] = n;
            int* a = &g_row_cols[i * RD];
            for (int j = 0; j < n; j++) tmp[j] = a[j];
            for (int j = 1; j < n; j++) {
                int key = tmp[j]; int k = j - 1;
                while (k >= 0 && tmp[k] > key) { tmp[k + 1] = tmp[k]; k--; }
                tmp[k + 1] = key;
            }
            for (int j = 0; j < n; j++) a[j] = tmp[j];
        }
    }
    grid_sync();

    // ---- block-strided ownership + register hoist ----
    // checks: quad cq = blockIdx + wib*148 < NC/4; c = cq*4 + grp
    const int cq   = blockIdx.x + wib * NBLK;
    const bool chas = (cq < NC / 4);
    int c = 0, cdeg = 0, cidx0 = 0, cidx1 = 0, cidx2 = 0, cidx3 = 0;
    float4 csgn = make_float4(0.f, 0.f, 0.f, 0.f);
    if (chas) {
        c     = cq * 4 + grp;
        cdeg  = g_row_cnt[c];
        cidx0 = g_row_cols[c * RD + 0 * 8 + sub];
        cidx1 = g_row_cols[c * RD + 1 * 8 + sub];
        cidx2 = g_row_cols[c * RD + 2 * 8 + sub];
        cidx3 = g_row_cols[c * RD + 3 * 8 + sub];
        csgn.x = 1.0f - 2.0f * synd[(sub * 4 + 0) * NC + c];
        csgn.y = 1.0f - 2.0f * synd[(sub * 4 + 1) * NC + c];
        csgn.z = 1.0f - 2.0f * synd[(sub * 4 + 2) * NC + c];
        csgn.w = 1.0f - 2.0f * synd[(sub * 4 + 3) * NC + c];
    }
    // vars: quad vq = blockIdx + wib*148 < NV/4 (single round)
    const int vq   = blockIdx.x + wib * NBLK;
    const bool vhas = (vq < NV / 4);
    int v = 0, vdeg = 0, vidx0 = 0, vidx1 = 0, vidx2 = 0, vidx3 = 0;
    float4 vch = make_float4(0.f, 0.f, 0.f, 0.f), vb = vch;
    if (vhas) {
        v     = vq * 4 + grp;
        vdeg  = g_col_cnt[v];
        vidx0 = g_col_rows[v * CD + 0 * 8 + sub];
        vidx1 = g_col_rows[v * CD + 1 * 8 + sub];
        vidx2 = g_col_rows[v * CD + 2 * 8 + sub];
        vidx3 = g_col_rows[v * CD + 3 * 8 + sub];
        vch.x = llr[(sub * 4 + 0) * NV + v];
        vch.y = llr[(sub * 4 + 1) * NV + v];
        vch.z = llr[(sub * 4 + 2) * NV + v];
        vch.w = llr[(sub * 4 + 3) * NV + v];
        vb = vch;
        vT4[(v << 3) + sub] = vb;             // publish initial beliefs
    }
    grid_sync();

    // ---- BP iterations ----
    for (int it = 0; it < ITERS; it++) {
        // v -> c : each lane sums its batch-quad over its check's edges
        if (chas) {
            float4 a0 = make_float4(0.f, 0.f, 0.f, 0.f);
            float4 a1 = make_float4(0.f, 0.f, 0.f, 0.f);
            #pragma unroll
            for (int jb = 0; jb < 4; jb++) {
                int reg = (jb == 0) ? cidx0 : (jb == 1) ? cidx1
                        : (jb == 2) ? cidx2 : cidx3;
                if (__any_sync(FULL, cdeg > jb * 8)) {
                    #pragma unroll
                    for (int m = 0; m < 8; m += 2) {
                        int i0 = __shfl_sync(FULL, reg, gbase + m);
                        int i1 = __shfl_sync(FULL, reg, gbase + m + 1);
                        if (jb * 8 + m < cdeg) {
                            float4 t = vT4[(i0 << 3) + sub];
                            a0.x += t.x; a0.y += t.y; a0.z += t.z; a0.w += t.w;
                        }
                        if (jb * 8 + m + 1 < cdeg) {
                            float4 t = vT4[(i1 << 3) + sub];
                            a1.x += t.x; a1.y += t.y; a1.z += t.z; a1.w += t.w;
                        }
                    }
                }
            }
            for (int j = 32; j < cdeg; j++) {          // very rare tail
                int idx = g_row_cols[c * RD + j];
                float4 t = vT4[(idx << 3) + sub];
                a0.x += t.x; a0.y += t.y; a0.z += t.z; a0.w += t.w;
            }
            float4 acc;
            acc.x = a0.x + a1.x; acc.y = a0.y + a1.y;
            acc.z = a0.z + a1.z; acc.w = a0.w + a1.w;
            float4 m4;
            m4.x = csgn.x * tanh_of_half(wvc * acc.x);
            m4.y = csgn.y * tanh_of_half(wvc * acc.y);
            m4.z = csgn.z * tanh_of_half(wvc * acc.z);
            m4.w = csgn.w * tanh_of_half(wvc * acc.w);
            cT4[(c << 3) + sub] = m4;
        }
        grid_sync();

        // c -> v + damped update
        if (vhas) {
            float4 a0 = make_float4(0.f, 0.f, 0.f, 0.f);
            float4 a1 = make_float4(0.f, 0.f, 0.f, 0.f);
            #pragma unroll
            for (int jb = 0; jb < 4; jb++) {
                int reg = (jb == 0) ? vidx0 : (jb == 1) ? vidx1
                        : (jb == 2) ? vidx2 : vidx3;
                if (__any_sync(FULL, vdeg > jb * 8)) {
                    #pragma unroll
                    for (int m = 0; m < 8; m += 2) {
                        int i0 = __shfl_sync(FULL, reg, gbase + m);
                        int i1 = __shfl_sync(FULL, reg, gbase + m + 1);
                        if (jb * 8 + m < vdeg) {
                            float4 t = cT4[(i0 << 3) + sub];
                            a0.x += t.x; a0.y += t.y; a0.z += t.z; a0.w += t.w;
                        }
                        if (jb * 8 + m + 1 < vdeg) {
                            float4 t = cT4[(i1 << 3) + sub];
                            a1.x += t.x; a1.y += t.y; a1.z += t.z; a1.w += t.w;
                        }
                    }
                }
            }
            for (int j = 32; j < vdeg; j++) {          // essentially never
                int idx = g_col_rows[v * CD + j];
                float4 t = cT4[(idx << 3) + sub];
                a0.x += t.x; a0.y += t.y; a0.z += t.z; a0.w += t.w;
            }
            float4 acc;
            acc.x = a0.x + a1.x; acc.y = a0.y + a1.y;
            acc.z = a0.z + a1.z; acc.w = a0.w + a1.w;
            vb.x = damp * vb.x + omd * (vch.x + wcv * acc.x);
            vb.y = damp * vb.y + omd * (vch.y + wcv * acc.y);
            vb.z = damp * vb.z + omd * (vch.z + wcv * acc.z);
            vb.w = damp * vb.w + omd * (vch.w + wcv * acc.w);
            vT4[(v << 3) + sub] = vb;
        }
        grid_sync();
    }

    // ---- output sigmoid(-v) from registers, (b, v) order ----
    if (vhas) {
        out[(sub * 4 + 0) * NV + v] = __fdividef(1.0f, 1.0f + __expf(vb.x));
        out[(sub * 4 + 1) * NV + v] = __fdividef(1.0f, 1.0f + __expf(vb.y));
        out[(sub * 4 + 2) * NV + v] = __fdividef(1.0f, 1.0f + __expf(vb.z));
        out[(sub * 4 + 3) * NV + v] = __fdividef(1.0f, 1.0f + __expf(vb.w));
    }

    // ---- re-zero degree counters for the next call's k_build ----
    for (int i = tid; i < NV; i += gsz) {
        g_col_cnt[i] = 0;
        if (i < NC) g_row_cnt[i] = 0;
    }
}

extern "C" void kernel_launch(void* const* d_in, const int* in_sizes, int n_in,
                              void* d_out, int out_size) {
    const float* synd = (const float*)d_in[0];
    const float* H    = (const float*)d_in[1];
    const float* llr  = (const float*)d_in[2];
    const float* wvc  = (const float*)d_in[3];
    const float* wcv  = (const float*)d_in[4];
    const float* damp = (const float*)d_in[5];
    float* out = (float*)d_out;

    k_build<<<B_BLOCKS, B_THREADS>>>((const uint4*)H);
    bp_persist<<<NBLK, NTHR>>>(synd, llr, wvc, wcv, damp, out);
}

// round 11
// speedup vs baseline: 1.4785x; 1.1840x over previous
#include <cuda_runtime.h>

// NeuralBPDecoder: sparse BP, 2 launches.
// k_build: stream H (537 MB, 8-deep uint4 batches) -> ELL adjacency (atomics).
//          Counters zero at entry (static init on call 1; bp_persist epilogue
//          re-zeroes them -> graph-replay deterministic).
// bp_persist (148 x 512, co-resident, software grid barrier):
//   sort + sentinel-pad lists -> hoist per-node state to registers ->
//   15 x two phases -> sigmoid output.
// Node layout: warp = 4 groups x 8 lanes; group owns one node; lane owns a
// float4 batch-quad. Inner loop is pure SHFL -> LDG.128 -> 2x add.rn.f32x2:
// lists padded with a sentinel row of zeros, so no bounds checks or votes.

#define NC 8192
#define NV 16384
#define NB 32
#define RD 64
#define CD 48
#define ITERS 15
#define NBLK 148
#define NTHR 512
#define WPB  (NTHR / 32)

#define B_BLOCKS 2048
#define B_THREADS 256
#define U 8
#define FULL 0xffffffffu

__device__ int   g_row_cnt[NC];
__device__ int   g_row_cols[NC * RD];
__device__ int   g_col_cnt[NV];
__device__ int   g_col_rows[NV * CD];
__device__ float g_vT[(NV + 1) * NB];   // beliefs, 128B rows; row NV = zeros
__device__ float g_cT[(NC + 1) * NB];   // check messages;   row NC = zeros

__device__ unsigned g_bar_arrive;
__device__ unsigned g_bar_gen;

__device__ __forceinline__ void grid_sync() {
    __syncthreads();
    if (threadIdx.x == 0) {
        __threadfence();
        volatile unsigned* genp = &g_bar_gen;
        unsigned gen = *genp;
        if (atomicAdd(&g_bar_arrive, 1) == NBLK - 1) {
            g_bar_arrive = 0;
            __threadfence();
            atomicAdd(&g_bar_gen, 1);
        } else {
            while (*genp == gen) { }
        }
        __threadfence();
    }
    __syncthreads();
}

__device__ __forceinline__ void emit_quad(long i, uint4 h) {
    long base = i * 4;
    unsigned vals[4] = {h.x, h.y, h.z, h.w};
    #pragma unroll
    for (int k = 0; k < 4; k++) {
        if (vals[k]) {
            long e = base + k;
            int c = (int)(e >> 14);
            int v = (int)(e & (NV - 1));
            int rs = atomicAdd(&g_row_cnt[c], 1);
            if (rs < RD) g_row_cols[c * RD + rs] = v;
            int cs = atomicAdd(&g_col_cnt[v], 1);
            if (cs < CD) g_col_rows[v * CD + cs] = c;
        }
    }
}

__global__ void __launch_bounds__(B_THREADS)
k_build(const uint4* __restrict__ H4) {
    const long n4 = (long)NC * NV / 4;
    const long stride = (long)B_BLOCKS * B_THREADS;
    long i = (long)blockIdx.x * B_THREADS + threadIdx.x;

    for (; i + (U - 1) * stride < n4; i += U * stride) {
        uint4 h[U];
        #pragma unroll
        for (int u = 0; u < U; u++)
            h[u] = __ldcs(&H4[i + u * stride]);
        #pragma unroll
        for (int u = 0; u < U; u++) {
            if (h[u].x | h[u].y | h[u].z | h[u].w)
                emit_quad(i + u * stride, h[u]);
        }
    }
    for (; i < n4; i += stride) {
        uint4 h = __ldcs(&H4[i]);
        if (h.x | h.y | h.z | h.w)
            emit_quad(i, h);
    }
}

// packed fp32x2 add (sm_100+): a += v
__device__ __forceinline__ void padd(unsigned long long& a, unsigned long long v) {
    asm("add.rn.f32x2 %0, %1, %2;" : "=l"(a) : "l"(a), "l"(v));
}

// tanh(y) = 1 - 2/(exp(2y)+1); caller passes z = 2y.
__device__ __forceinline__ float tanh_of_half(float z) {
    return 1.0f - __fdividef(2.0f, __expf(z) + 1.0f);
}

__global__ void __launch_bounds__(NTHR, 1)
bp_persist(const float* __restrict__ synd, const float* __restrict__ llr,
           const float* __restrict__ wvc_p, const float* __restrict__ wcv_p,
           const float* __restrict__ damp_p, float* __restrict__ out) {
    const int tid   = blockIdx.x * NTHR + threadIdx.x;
    const int gsz   = NBLK * NTHR;
    const int wib   = threadIdx.x >> 5;
    const int lane  = threadIdx.x & 31;
    const int sub   = lane & 7;           // float4 slot (batch quad)
    const int grp   = lane >> 3;          // node within quad
    const int gbase = lane & 24;

    const float wvc  = __ldg(wvc_p);
    const float wcv  = __ldg(wcv_p);
    const float damp = __ldg(damp_p);
    const float omd  = 1.0f - damp;

    float4* __restrict__ vT4 = (float4*)g_vT;
    float4* __restrict__ cT4 = (float4*)g_cT;
    const ulonglong2* __restrict__ vTu = (const ulonglong2*)g_vT;
    const ulonglong2* __restrict__ cTu = (const ulonglong2*)g_cT;

    // ---- sort adjacency lists + sentinel-pad to 32 entries ----
    {
        int tmp[RD];
        for (int i = tid; i < NV; i += gsz) {
            int n = min(g_col_cnt[i], CD);
            g_col_cnt[i] = n;
            int* a = &g_col_rows[i * CD];
            for (int j = 0; j < n; j++) tmp[j] = a[j];
            for (int j = 1; j < n; j++) {
                int key = tmp[j]; int k = j - 1;
                while (k >= 0 && tmp[k] > key) { tmp[k + 1] = tmp[k]; k--; }
                tmp[k + 1] = key;
            }
            for (int j = 0; j < n; j++) a[j] = tmp[j];
            for (int j = n; j < 32; j++) a[j] = NC;    // sentinel (zero row)
        }
        for (int i = tid; i < NC; i += gsz) {
            int n = min(g_row_cnt[i], RD);
            g_row_cnt[i] = n;
            int* a = &g_row_cols[i * RD];
            for (int j = 0; j < n; j++) tmp[j] = a[j];
            for (int j = 1; j < n; j++) {
                int key = tmp[j]; int k = j - 1;
                while (k >= 0 && tmp[k] > key) { tmp[k + 1] = tmp[k]; k--; }
                tmp[k + 1] = key;
            }
            for (int j = 0; j < n; j++) a[j] = tmp[j];
            for (int j = n; j < 32; j++) a[j] = NV;    // sentinel (zero row)
        }
    }
    // zero the sentinel rows
    if (blockIdx.x == 0 && threadIdx.x < NB) {
        g_vT[NV * NB + threadIdx.x] = 0.0f;
        g_cT[NC * NB + threadIdx.x] = 0.0f;
    }
    grid_sync();

    // ---- block-strided ownership + register hoist ----
    const int cq    = blockIdx.x + wib * NBLK;
    const bool chas = (cq < NC / 4);
    int c = 0, cdeg = 0, cblk = 0, cmax = 0;
    int cidx0 = NV, cidx1 = NV, cidx2 = NV, cidx3 = NV;
    float4 csgn = make_float4(0.f, 0.f, 0.f, 0.f);
    if (chas) {
        c     = cq * 4 + grp;
        cdeg  = g_row_cnt[c];
        cidx0 = g_row_cols[c * RD + 0 * 8 + sub];
        cidx1 = g_row_cols[c * RD + 1 * 8 + sub];
        cidx2 = g_row_cols[c * RD + 2 * 8 + sub];
        cidx3 = g_row_cols[c * RD + 3 * 8 + sub];
        csgn.x = 1.0f - 2.0f * synd[(sub * 4 + 0) * NC + c];
        csgn.y = 1.0f - 2.0f * synd[(sub * 4 + 1) * NC + c];
        csgn.z = 1.0f - 2.0f * synd[(sub * 4 + 2) * NC + c];
        csgn.w = 1.0f - 2.0f * synd[(sub * 4 + 3) * NC + c];
        int m = cdeg;
        m = max(m, __shfl_xor_sync(FULL, m, 8));
        m = max(m, __shfl_xor_sync(FULL, m, 16));
        cmax = m;
        cblk = min((m + 7) >> 3, 4);
    }
    // vars: two block-strided rounds
    int  vvv[2], vdeg[2], vblk[2], vmax[2];
    int  vidx[2][4];
    bool vhas[2];
    float4 vch[2], vb[2];
    #pragma unroll
    for (int r = 0; r < 2; r++) {
        int vq  = blockIdx.x + (wib + r * WPB) * NBLK;
        vhas[r] = (vq < NV / 4);
        vvv[r] = 0; vdeg[r] = 0; vblk[r] = 0; vmax[r] = 0;
        vidx[r][0] = vidx[r][1] = vidx[r][2] = vidx[r][3] = NC;
        vch[r] = make_float4(0.f, 0.f, 0.f, 0.f); vb[r] = vch[r];
        if (vhas[r]) {
            int v   = vq * 4 + grp;
            vvv[r]  = v;
            vdeg[r] = g_col_cnt[v];
            vidx[r][0] = g_col_rows[v * CD + 0 * 8 + sub];
            vidx[r][1] = g_col_rows[v * CD + 1 * 8 + sub];
            vidx[r][2] = g_col_rows[v * CD + 2 * 8 + sub];
            vidx[r][3] = g_col_rows[v * CD + 3 * 8 + sub];
            vch[r].x = llr[(sub * 4 + 0) * NV + v];
            vch[r].y = llr[(sub * 4 + 1) * NV + v];
            vch[r].z = llr[(sub * 4 + 2) * NV + v];
            vch[r].w = llr[(sub * 4 + 3) * NV + v];
            vb[r] = vch[r];
            vT4[(v << 3) + sub] = vb[r];     // publish initial beliefs
            int m = vdeg[r];
            m = max(m, __shfl_xor_sync(FULL, m, 8));
            m = max(m, __shfl_xor_sync(FULL, m, 16));
            vmax[r] = m;
            vblk[r] = min((m + 7) >> 3, 4);
        }
    }
    grid_sync();

    // ---- BP iterations ----
    for (int it = 0; it < ITERS; it++) {
        // v -> c
        if (chas) {
            unsigned long long A0 = 0, A1 = 0, B0 = 0, B1 = 0;
            #pragma unroll
            for (int jb = 0; jb < 4; jb++) {
                if (jb >= cblk) break;                 // warp-uniform
                int reg = (jb == 0) ? cidx0 : (jb == 1) ? cidx1
                        : (jb == 2) ? cidx2 : cidx3;
                #pragma unroll
                for (int m = 0; m < 8; m += 2) {
                    int i0 = __shfl_sync(FULL, reg, gbase + m);
                    int i1 = __shfl_sync(FULL, reg, gbase + m + 1);
                    ulonglong2 t0 = vTu[(i0 << 3) + sub];
                    ulonglong2 t1 = vTu[(i1 << 3) + sub];
                    padd(A0, t0.x); padd(A1, t0.y);
                    padd(B0, t1.x); padd(B1, t1.y);
                }
            }
            if (cmax > 32) {                           // very rare tail
                for (int j = 32; j < cdeg; j++) {
                    int idx = g_row_cols[c * RD + j];
                    ulonglong2 t = vTu[(idx << 3) + sub];
                    padd(A0, t.x); padd(A1, t.y);
                }
            }
            padd(A0, B0); padd(A1, B1);
            float2 lo = *(float2*)&A0;
            float2 hi = *(float2*)&A1;
            float4 m4;
            m4.x = csgn.x * tanh_of_half(wvc * lo.x);
            m4.y = csgn.y * tanh_of_half(wvc * lo.y);
            m4.z = csgn.z * tanh_of_half(wvc * hi.x);
            m4.w = csgn.w * tanh_of_half(wvc * hi.y);
            cT4[(c << 3) + sub] = m4;
        }
        grid_sync();

        // c -> v + damped update
        #pragma unroll
        for (int r = 0; r < 2; r++) {
            if (vhas[r]) {
                unsigned long long A0 = 0, A1 = 0, B0 = 0, B1 = 0;
                #pragma unroll
                for (int jb = 0; jb < 4; jb++) {
                    if (jb >= vblk[r]) break;          // warp-uniform
                    int reg = vidx[r][jb];
                    #pragma unroll
                    for (int m = 0; m < 8; m += 2) {
                        int i0 = __shfl_sync(FULL, reg, gbase + m);
                        int i1 = __shfl_sync(FULL, reg, gbase + m + 1);
                        ulonglong2 t0 = cTu[(i0 << 3) + sub];
                        ulonglong2 t1 = cTu[(i1 << 3) + sub];
                        padd(A0, t0.x); padd(A1, t0.y);
                        padd(B0, t1.x); padd(B1, t1.y);
                    }
                }
                if (vmax[r] > 32) {                    // essentially never
                    for (int j = 32; j < vdeg[r]; j++) {
                        int idx = g_col_rows[vvv[r] * CD + j];
                        ulonglong2 t = cTu[(idx << 3) + sub];
                        padd(A0, t.x); padd(A1, t.y);
                    }
                }
                padd(A0, B0); padd(A1, B1);
                float2 lo = *(float2*)&A0;
                float2 hi = *(float2*)&A1;
                vb[r].x = damp * vb[r].x + omd * (vch[r].x + wcv * lo.x);
                vb[r].y = damp * vb[r].y + omd * (vch[r].y + wcv * lo.y);
                vb[r].z = damp * vb[r].z + omd * (vch[r].z + wcv * hi.x);
                vb[r].w = damp * vb[r].w + omd * (vch[r].w + wcv * hi.y);
                vT4[(vvv[r] << 3) + sub] = vb[r];
            }
        }
        grid_sync();
    }

    // ---- output sigmoid(-v) from registers, (b, v) order ----
    #pragma unroll
    for (int r = 0; r < 2; r++) {
        if (vhas[r]) {
            int v = vvv[r];
            out[(sub * 4 + 0) * NV + v] = __fdividef(1.0f, 1.0f + __expf(vb[r].x));
            out[(sub * 4 + 1) * NV + v] = __fdividef(1.0f, 1.0f + __expf(vb[r].y));
            out[(sub * 4 + 2) * NV + v] = __fdividef(1.0f, 1.0f + __expf(vb[r].z));
            out[(sub * 4 + 3) * NV + v] = __fdividef(1.0f, 1.0f + __expf(vb[r].w));
        }
    }

    // ---- re-zero degree counters for the next call's k_build ----
    for (int i = tid; i < NV; i += gsz) {
        g_col_cnt[i] = 0;
        if (i < NC) g_row_cnt[i] = 0;
    }
}

extern "C" void kernel_launch(void* const* d_in, const int* in_sizes, int n_in,
                              void* d_out, int out_size) {
    const float* synd = (const float*)d_in[0];
    const float* H    = (const float*)d_in[1];
    const float* llr  = (const float*)d_in[2];
    const float* wvc  = (const float*)d_in[3];
    const float* wcv  = (const float*)d_in[4];
    const float* damp = (const float*)d_in[5];
    float* out = (float*)d_out;

    k_build<<<B_BLOCKS, B_THREADS>>>((const uint4*)H);
    bp_persist<<<NBLK, NTHR>>>(synd, llr, wvc, wcv, damp, out);
}